// round 5
// baseline (speedup 1.0000x reference)
#include <cuda_runtime.h>
#include <cuda_fp16.h>
#include <math.h>

#define BB   8
#define TT   150
#define DD   30
#define HH   5
#define HDD  6
#define LL   3
#define NI   40     // BB*HH
#define KL   300
#define KA   74
#define KV   35
#define AA   10     // a-values per attention block (5 fp16x2 pairs)
#define GRID 600
#define NW   5      // warps per block

// ---------------- device scratch (no allocations allowed) ----------------
__device__ float g_h[2][TT*BB*DD];            // per-stream hidden state [T,B,D]
__device__ float g_K[2][LL][NI*TT*HDD];       // per (s,l): [i, t, e]
__device__ float g_V[2][LL][NI*TT*HDD];
__device__ float g_Q[2][NI*TT*HDD];           // current-layer Q
__device__ float g_attn[2][TT*BB*DD];         // attention output [T,B,D]
__device__ unsigned g_arrive = 0;
__device__ volatile unsigned g_gen = 0;

__device__ __forceinline__ float warpsum(float v){
    #pragma unroll
    for (int o=16;o>0;o>>=1) v += __shfl_xor_sync(0xffffffffu, v, o);
    return v;
}

// grid-wide barrier (all GRID blocks resident by construction)
__device__ __forceinline__ void gsync(){
    __syncthreads();
    if (threadIdx.x == 0){
        __threadfence();
        unsigned gen = g_gen;
        if (atomicAdd(&g_arrive, 1u) == GRID-1u){
            g_arrive = 0u;
            __threadfence();
            g_gen = gen + 1u;
        } else {
            while (g_gen == gen) {}
            __threadfence();
        }
    }
    __syncthreads();
}

union SU {
    struct { float sx[NW][KL+KA+KV]; float ax[NW][96]; } pre;
    struct { __half2 sVh[TT][8]; float sQa[AA*HDD]; float sP[NW][8]; float sVbar[8];
             float sMax[AA][NW]; float sBMax[AA]; float sSum[AA][NW][8]; } att;
    struct { float sA[NW][DD]; float sXn[NW][DD]; float sHid[NW][4*DD]; } ffn;
    struct { float sLast[BB*2*DD]; float sHid[2*DD]; float sC[2*DD]; } head;
};

__global__ void __launch_bounds__(160, NW) k_all(
    const float* __restrict__ xl, const float* __restrict__ xa,
    const float* __restrict__ xv, const float* __restrict__ Wl,
    const float* __restrict__ Wa, const float* __restrict__ Wv,
    const float* __restrict__ in_w, const float* __restrict__ in_b,
    const float* __restrict__ out_w, const float* __restrict__ out_b,
    const float* __restrict__ w1, const float* __restrict__ b1,
    const float* __restrict__ w2, const float* __restrict__ b2,
    const float* __restrict__ n1g, const float* __restrict__ n1b,
    const float* __restrict__ n2g, const float* __restrict__ n2b,
    const float* __restrict__ p1w, const float* __restrict__ p1b,
    const float* __restrict__ p2w, const float* __restrict__ p2b,
    const float* __restrict__ ow, const float* __restrict__ ob,
    float* __restrict__ out){
    __shared__ __align__(16) SU su;
    int tid = threadIdx.x;
    int lane = tid & 31, wmy = tid >> 5;

    // ================= PHASE 0: pre (warp per (t,b) row) =================
    {
        int gw = blockIdx.x*NW + wmy;     // 0..2999, rows 0..1199
        if (gw < TT*BB){
            int t = gw / BB, b = gw % BB;
            float* sx = su.pre.sx[wmy];
            for (int k=lane;k<KL;k+=32) sx[k]        = xl[(b*TT+t)*KL+k];
            for (int k=lane;k<KA;k+=32) sx[KL+k]     = xa[(b*TT+t)*KA+k];
            for (int k=lane;k<KV;k+=32) sx[KL+KA+k]  = xv[(b*TT+t)*KV+k];
            __syncwarp();
            float p0=0.f, p1=0.f, p2=0.f;
            if (lane<DD){
                const float* wr0 = Wl + lane*KL;
                #pragma unroll 4
                for (int k=0;k<KL;k++) p0 = fmaf(sx[k], wr0[k], p0);
                const float* wr1 = Wa + lane*KA;
                #pragma unroll 2
                for (int k=0;k<KA;k++) p1 = fmaf(sx[KL+k], wr1[k], p1);
                const float* wr2 = Wv + lane*KV;
                for (int k=0;k<KV;k++) p2 = fmaf(sx[KL+KA+k], wr2[k], p2);
                int o=(t*BB+b)*DD+lane; g_h[0][o]=p0; g_h[1][o]=p0;
            }
            // LN normalize (no affine yet)
            float xn0, xn1, xn2;
            {
                float s0=warpsum(p0), q0=warpsum(p0*p0);
                float m=s0*(1.f/DD), v=q0*(1.f/DD)-m*m; xn0=(p0-m)*rsqrtf(v+1e-5f);
                float s1=warpsum(p1), q1=warpsum(p1*p1);
                m=s1*(1.f/DD); v=q1*(1.f/DD)-m*m; xn1=(p1-m)*rsqrtf(v+1e-5f);
                float s2=warpsum(p2), q2=warpsum(p2*p2);
                m=s2*(1.f/DD); v=q2*(1.f/DD)-m*m; xn2=(p2-m)*rsqrtf(v+1e-5f);
            }
            float* ax = su.pre.ax[wmy];
            #pragma unroll 1
            for (int sl=0; sl<6; sl++){
                int s_ = sl/LL, l_ = sl%LL;
                int pb = sl*DD;
                if (lane<DD){
                    float g = n1g[pb+lane], be = n1b[pb+lane];
                    float xk = (s_==0)? xn1 : xn2;
                    float xv_= (s_==0)? xn2 : xn1;
                    ax[lane]    = xk*g + be;
                    ax[32+lane] = xv_*g + be;
                    if (l_==0) ax[64+lane] = xn0*g + be;
                }
                __syncwarp();
                if (lane<DD){
                    const float* iw = in_w + sl*3*DD*DD;
                    const float* ib = in_b + sl*3*DD;
                    int i = b*HH + lane/HDD, e = lane%HDD;
                    int o = (i*TT + t)*HDD + e;
                    float ka = ib[DD+lane], va = ib[2*DD+lane];
                    const float* wk = iw + (DD+lane)*DD;
                    const float* wv = iw + (2*DD+lane)*DD;
                    #pragma unroll
                    for (int j=0;j<DD;j++){ ka = fmaf(ax[j], wk[j], ka); va = fmaf(ax[32+j], wv[j], va); }
                    g_K[s_][l_][o] = ka;
                    g_V[s_][l_][o] = va;
                    if (l_==0){
                        float qa = ib[lane];
                        const float* wq = iw + lane*DD;
                        #pragma unroll
                        for (int j=0;j<DD;j++) qa = fmaf(ax[64+j], wq[j], qa);
                        g_Q[s_][o] = qa * 0.4082482904638631f;
                    }
                }
                __syncwarp();
            }
        }
    }
    gsync();

    // ================= layers =================
    #pragma unroll 1
    for (int l=0; l<LL; l++){
        // ---- attention: exactly 2 items per block ----
        #pragma unroll 1
        for (int m = blockIdx.x; m < 2*NI*(TT/AA); m += GRID){
            __syncthreads();              // protect smem reuse across items
            int s = m / (NI*(TT/AA));
            int rem = m % (NI*(TT/AA));
            int i = rem / (TT/AA);
            int a0 = (rem % (TT/AA)) * AA;
            const float* Kp = g_K[s][l] + i*TT*HDD;
            const float* Vp = g_V[s][l] + i*TT*HDD;
            const float* Qp = g_Q[s]    + i*TT*HDD;
            bool valid = tid < TT;
            int b = valid ? tid : 0;

            float kb[HDD], vv[HDD];
            #pragma unroll
            for (int e=0;e<HDD;e++){
                kb[e] = Kp[b*HDD+e];
                vv[e] = valid ? Vp[b*HDD+e] : 0.f;
            }
            {   // vbar partials
                float p[HDD];
                #pragma unroll
                for (int e=0;e<HDD;e++) p[e] = warpsum(vv[e]);
                if (lane==0){
                    #pragma unroll
                    for (int e=0;e<HDD;e++) su.att.sP[wmy][e] = p[e];
                }
            }
            if (tid < AA*HDD) su.att.sQa[tid] = Qp[a0*HDD + tid];
            __syncthreads();
            if (tid < HDD){
                float acc = 0.f;
                #pragma unroll
                for (int ww=0;ww<NW;ww++) acc += su.att.sP[ww][tid];
                su.att.sVbar[tid] = acc * (1.f/TT);
            }
            __syncthreads();
            if (valid){
                #pragma unroll
                for (int e=0;e<HDD;e++)
                    su.att.sVh[tid][e] = __float2half2_rn(vv[e] + su.att.sVbar[e]);
            }
            __syncthreads();

            __half2 kq[5][HDD];
            #pragma unroll
            for (int p=0;p<5;p++)
                #pragma unroll
                for (int e=0;e<HDD;e++)
                    kq[p][e] = __floats2half2_rn(su.att.sQa[(2*p)*HDD+e]*kb[e],
                                                 su.att.sQa[(2*p+1)*HDD+e]*kb[e]);

            __half2 mx2[5];
            #pragma unroll
            for (int p=0;p<5;p++) mx2[p] = __floats2half2_rn(-60000.f, -60000.f);

            #pragma unroll 2
            for (int c=0;c<TT;c++){
                uint4 u0 = *reinterpret_cast<const uint4*>(&su.att.sVh[c][0]);
                uint2 u1 = *reinterpret_cast<const uint2*>(&su.att.sVh[c][4]);
                __half2 v0 = *(__half2*)&u0.x, v1 = *(__half2*)&u0.y;
                __half2 v2 = *(__half2*)&u0.z, v3 = *(__half2*)&u0.w;
                __half2 v4 = *(__half2*)&u1.x, v5 = *(__half2*)&u1.y;
                #pragma unroll
                for (int p=0;p<5;p++){
                    __half2 acc = __hmul2(kq[p][0], v0);
                    acc = __hfma2(kq[p][1], v1, acc);
                    acc = __hfma2(kq[p][2], v2, acc);
                    acc = __hfma2(kq[p][3], v3, acc);
                    acc = __hfma2(kq[p][4], v4, acc);
                    acc = __hfma2(kq[p][5], v5, acc);
                    mx2[p] = __hmax2(mx2[p], acc);
                }
            }
            float fx[AA];
            #pragma unroll
            for (int p=0;p<5;p++){
                fx[2*p]   = __low2float(mx2[p]);
                fx[2*p+1] = __high2float(mx2[p]);
            }

            // batched epilogue
            #pragma unroll
            for (int a=0;a<AA;a++){
                float mm = valid ? fx[a] : -INFINITY;
                #pragma unroll
                for (int o=16;o>0;o>>=1) mm = fmaxf(mm, __shfl_xor_sync(0xffffffffu, mm, o));
                if (lane==0) su.att.sMax[a][wmy] = mm;
            }
            __syncthreads();
            if (tid < AA){
                float mm = su.att.sMax[tid][0];
                #pragma unroll
                for (int ww=1;ww<NW;ww++) mm = fmaxf(mm, su.att.sMax[tid][ww]);
                su.att.sBMax[tid] = mm;
            }
            __syncthreads();
            float qb[HDD];
            #pragma unroll
            for (int e=0;e<HDD;e++) qb[e] = Qp[b*HDD+e];
            #pragma unroll
            for (int a=0;a<AA;a++){
                float ex = valid ? __expf(fx[a] - su.att.sBMax[a]) : 0.f;
                float v7[7];
                #pragma unroll
                for (int e=0;e<HDD;e++) v7[e] = ex*qb[e];
                v7[6] = ex;
                #pragma unroll
                for (int j=0;j<7;j++){
                    float v = v7[j];
                    #pragma unroll
                    for (int o=16;o>0;o>>=1) v += __shfl_xor_sync(0xffffffffu, v, o);
                    if (lane==0) su.att.sSum[a][wmy][j] = v;
                }
            }
            __syncthreads();
            if (tid < AA*HDD){
                int a = tid / HDD, e = tid % HDD;
                float num=0.f, den=0.f;
                #pragma unroll
                for (int ww=0;ww<NW;ww++){ num += su.att.sSum[a][ww][e]; den += su.att.sSum[a][ww][6]; }
                int b_ = i/HH, h_ = i%HH;
                g_attn[s][((a0+a)*BB + b_)*DD + h_*HDD + e] = num/den;
            }
        }
        gsync();

        // ---- ffn + next-layer Q (warp per (s,t,b) row) ----
        {
            int gw = blockIdx.x*NW + wmy;   // rows 0..2399
            if (gw < 2*TT*BB){
                int b = gw % BB;
                int t = (gw/BB) % TT;
                int s = gw / (TT*BB);
                int ro = (t*BB+b)*DD;
                if (lane<DD) su.ffn.sA[wmy][lane] = g_attn[s][ro+lane];
                __syncwarp();
                int pl_ = s*LL+l;
                float x = 0.f;
                if (lane<DD){
                    const float* wr = out_w + pl_*DD*DD + lane*DD;
                    float acc = out_b[pl_*DD + lane];
                    #pragma unroll
                    for (int j=0;j<DD;j++) acc = fmaf(su.ffn.sA[wmy][j], wr[j], acc);
                    x = g_h[s][ro+lane] + acc;
                }
                float sum = warpsum(x), sq = warpsum(x*x);
                float m = sum*(1.f/DD), var = sq*(1.f/DD)-m*m, r = rsqrtf(var+1e-5f);
                if (lane<DD) su.ffn.sXn[wmy][lane] = (x-m)*r*n2g[pl_*DD+lane] + n2b[pl_*DD+lane];
                __syncwarp();
                for (int j=lane; j<4*DD; j+=32){
                    const float* wr = w1 + pl_*4*DD*DD + j*DD;
                    float acc = b1[pl_*4*DD + j];
                    #pragma unroll
                    for (int q=0;q<DD;q++) acc = fmaf(su.ffn.sXn[wmy][q], wr[q], acc);
                    su.ffn.sHid[wmy][j] = fmaxf(acc, 0.f);
                }
                __syncwarp();
                float hnew = 0.f;
                if (lane<DD){
                    const float* wr = w2 + pl_*DD*4*DD + lane*4*DD;
                    float acc = b2[pl_*DD + lane];
                    #pragma unroll 4
                    for (int j=0;j<4*DD;j++) acc = fmaf(su.ffn.sHid[wmy][j], wr[j], acc);
                    hnew = x + acc;
                    g_h[s][ro+lane] = hnew;
                }
                if (l+1 < LL){
                    float sum2 = warpsum(hnew), sq2 = warpsum(hnew*hnew);
                    float m2 = sum2*(1.f/DD), var2 = sq2*(1.f/DD)-m2*m2, r2 = rsqrtf(var2+1e-5f);
                    int pb = (pl_+1)*DD;
                    if (lane<DD) su.ffn.sA[wmy][lane] = (hnew-m2)*r2*n1g[pb+lane] + n1b[pb+lane];
                    __syncwarp();
                    if (lane<DD){
                        const float* iw = in_w + (pl_+1)*3*DD*DD + lane*DD;
                        float acc = in_b[(pl_+1)*3*DD + lane];
                        #pragma unroll
                        for (int j=0;j<DD;j++) acc = fmaf(su.ffn.sA[wmy][j], iw[j], acc);
                        acc *= 0.4082482904638631f;
                        int i = b*HH + lane/HDD, e = lane%HDD;
                        g_Q[s][(i*TT+t)*HDD+e] = acc;
                    }
                }
            }
        }
        gsync();
    }

    // ================= head (block 0) =================
    if (blockIdx.x == 0){
        for (int idx=tid; idx<BB*2*DD; idx+=160){
            int b = idx/(2*DD), j = idx%(2*DD);
            float v = (j<DD) ? g_h[0][((TT-1)*BB+b)*DD + j]
                             : g_h[1][((TT-1)*BB+b)*DD + (j-DD)];
            su.head.sLast[idx] = v;
            out[BB + idx] = v;            // last_hs after out[0:8]
        }
        __syncthreads();
        for (int b=0;b<BB;b++){
            if (tid < 2*DD){
                float acc = p1b[tid];
                const float* wr = p1w + tid*2*DD;
                for (int j=0;j<2*DD;j++) acc = fmaf(su.head.sLast[b*2*DD+j], wr[j], acc);
                su.head.sHid[tid] = fmaxf(acc, 0.f);
            }
            __syncthreads();
            if (tid < 2*DD){
                float acc = p2b[tid];
                const float* wr = p2w + tid*2*DD;
                for (int j=0;j<2*DD;j++) acc = fmaf(su.head.sHid[j], wr[j], acc);
                acc += su.head.sLast[b*2*DD+tid];
                su.head.sC[tid] = acc * ow[tid];
            }
            __syncthreads();
            if (tid==0){
                float acc = ob[0];
                for (int j=0;j<2*DD;j++) acc += su.head.sC[j];
                out[b] = acc;
            }
            __syncthreads();
        }
    }
}

// -------------------------------------------------------------------------
extern "C" void kernel_launch(void* const* d_in, const int* in_sizes, int n_in,
                              void* d_out, int out_size){
    const float* xl   = (const float*)d_in[0];
    const float* xa   = (const float*)d_in[1];
    const float* xv   = (const float*)d_in[2];
    const float* Wl   = (const float*)d_in[3];
    const float* Wa   = (const float*)d_in[4];
    const float* Wv   = (const float*)d_in[5];
    const float* in_w = (const float*)d_in[6];
    const float* in_b = (const float*)d_in[7];
    const float* outw = (const float*)d_in[8];
    const float* outb = (const float*)d_in[9];
    const float* l1w  = (const float*)d_in[10];
    const float* l1b  = (const float*)d_in[11];
    const float* l2w  = (const float*)d_in[12];
    const float* l2b  = (const float*)d_in[13];
    const float* n1g  = (const float*)d_in[14];
    const float* n1b  = (const float*)d_in[15];
    const float* n2g  = (const float*)d_in[16];
    const float* n2b  = (const float*)d_in[17];
    const float* p1w  = (const float*)d_in[18];
    const float* p1b  = (const float*)d_in[19];
    const float* p2w  = (const float*)d_in[20];
    const float* p2b  = (const float*)d_in[21];
    const float* ow   = (const float*)d_in[22];
    const float* ob   = (const float*)d_in[23];
    float* out = (float*)d_out;

    k_all<<<GRID, 160>>>(xl, xa, xv, Wl, Wa, Wv, in_w, in_b, outw, outb,
                         l1w, l1b, l2w, l2b, n1g, n1b, n2g, n2b,
                         p1w, p1b, p2w, p2b, ow, ob, out);
}

// round 6
// speedup vs baseline: 1.0977x; 1.0977x over previous
#include <cuda_runtime.h>
#include <cuda_fp16.h>
#include <math.h>

#define BB   8
#define TT   150
#define DD   30
#define HH   5
#define HDD  6
#define LL   3
#define NI   40     // BB*HH
#define KL   300
#define KA   74
#define KV   35
#define AA   10     // a-values per attention block (5 fp16x2 pairs)

// ---------------- device scratch (no allocations allowed) ----------------
__device__ float g_h[2][TT*BB*DD];            // per-stream hidden state [T,B,D]
__device__ float g_K[2][LL][NI*TT*HDD];       // per (s,l): [i, t, e]
__device__ float g_V[2][LL][NI*TT*HDD];
__device__ float g_Q[2][NI*TT*HDD];           // current-layer Q
__device__ float g_attn[2][TT*BB*DD];         // attention output [T,B,D]

__device__ __forceinline__ float warpsum(float v){
    #pragma unroll
    for (int o=16;o>0;o>>=1) v += __shfl_xor_sync(0xffffffffu, v, o);
    return v;
}
// PDL: wait for programmatic predecessor's trigger (no-op if none)
__device__ __forceinline__ void gwait(){
    asm volatile("griddepcontrol.wait;" ::: "memory");
}
// PDL: allow dependents to launch (prior stores of this thread are visible)
__device__ __forceinline__ void gtrig(){
    asm volatile("griddepcontrol.launch_dependents;" ::: "memory");
}
__device__ __forceinline__ void pfL1(const void* p){
    asm volatile("prefetch.global.L1 [%0];" :: "l"(p));
}

// ---------------- 1. fused pre-stage: proj + all K/V + Q(l=0) -------------
// one block per (t,b); everything is row-local.
__global__ void __launch_bounds__(96) k_pre(
    const float* __restrict__ xl, const float* __restrict__ xa,
    const float* __restrict__ xv, const float* __restrict__ Wl,
    const float* __restrict__ Wa, const float* __restrict__ Wv,
    const float* __restrict__ in_w, const float* __restrict__ in_b,
    const float* __restrict__ n1g, const float* __restrict__ n1b){
    int r = blockIdx.x;                  // 0..T*B-1
    int t = r / BB, b = r % BB;
    int w = threadIdx.x >> 5, lane = threadIdx.x & 31;
    __shared__ float sx[KL+KA+KV];
    __shared__ float xn[3][DD];
    __shared__ float axk[DD], axv[DD], axq[DD];
    for (int k=threadIdx.x; k<KL; k+=96) sx[k]        = xl[(b*TT+t)*KL + k];
    for (int k=threadIdx.x; k<KA; k+=96) sx[KL+k]     = xa[(b*TT+t)*KA + k];
    for (int k=threadIdx.x; k<KV; k+=96) sx[KL+KA+k]  = xv[(b*TT+t)*KV + k];
    __syncthreads();
    // modality projection: warp w -> mod w
    float pv = 0.f;
    {
        const float* W  = (w==0)? Wl : (w==1)? Wa : Wv;
        int K           = (w==0)? KL : (w==1)? KA : KV;
        const float* xs = sx + ((w==0)? 0 : (w==1)? KL : KL+KA);
        if (lane < DD){
            const float* wr = W + lane*K;
            for (int k=0;k<K;k++) pv = fmaf(xs[k], wr[k], pv);
            if (w==0){ int o=(t*BB+b)*DD+lane; g_h[0][o]=pv; g_h[1][o]=pv; }
        }
    }
    // LN normalize (no affine yet)
    {
        float x = (lane<DD)? pv : 0.f;
        float sum = warpsum(x), sq = warpsum(x*x);
        float m = sum*(1.f/DD), var = sq*(1.f/DD)-m*m, rs = rsqrtf(var+1e-5f);
        if (lane<DD) xn[w][lane] = (x-m)*rs;
    }
    __syncthreads();
    #pragma unroll 1
    for (int sl=0; sl<6; sl++){
        int s_ = sl/LL, l_ = sl%LL;
        int ksrc = (s_==0)?1:2, vsrc = (s_==0)?2:1;
        int pb = sl*DD;
        if (lane<DD){
            float g = n1g[pb+lane], be = n1b[pb+lane];
            if (w==0) axk[lane] = xn[ksrc][lane]*g + be;
            else if (w==1) axv[lane] = xn[vsrc][lane]*g + be;
            else if (l_==0) axq[lane] = xn[0][lane]*g + be;
        }
        __syncthreads();
        if (lane<DD){
            const float* iw = in_w + sl*3*DD*DD;
            const float* ib = in_b + sl*3*DD;
            int i = b*HH + lane/HDD, e = lane%HDD;
            int o = (i*TT + t)*HDD + e;
            if (w==0){
                float acc = ib[DD+lane];
                const float* wr = iw + (DD+lane)*DD;
                #pragma unroll
                for (int j=0;j<DD;j++) acc = fmaf(axk[j], wr[j], acc);
                g_K[s_][l_][o] = acc;
            } else if (w==1){
                float acc = ib[2*DD+lane];
                const float* wr = iw + (2*DD+lane)*DD;
                #pragma unroll
                for (int j=0;j<DD;j++) acc = fmaf(axv[j], wr[j], acc);
                g_V[s_][l_][o] = acc;
            } else if (l_==0){
                float acc = ib[lane];
                const float* wr = iw + lane*DD;
                #pragma unroll
                for (int j=0;j<DD;j++) acc = fmaf(axq[j], wr[j], acc);
                g_Q[s_][o] = acc * 0.4082482904638631f;
            }
        }
        __syncthreads();
    }
    gtrig();
}

// ---------------- 2. attention core (fp16x2 HFMA2 scan, hot kernel) -------
// One block per (s, i, 10-a group). 160 threads, thread = one b (key index).
// fused[a,b] = max_c (q_a o k_b) . (v_c + vbar)     [mean folded into max]
// then softmax over b and attn[a,:] = sum_b p_b * q_b
// PDL: for l>0, K/V come from k_pre (complete) -> prefetched before gwait;
//      Q comes from the immediate predecessor -> read after gwait.
__global__ void __launch_bounds__(160) k_att(int l){
    int s = blockIdx.z, i = blockIdx.y, a0 = blockIdx.x*AA;
    int tid = threadIdx.x;
    int lane = tid & 31, w = tid >> 5;
    __shared__ __align__(16) __half2 sVh[TT][8];  // v' duplicated fp16 pairs
    __shared__ float sQa[AA*HDD];
    __shared__ float sP[5][8];
    __shared__ float sVbar[HDD];
    __shared__ float sMax[AA][5];
    __shared__ float sBMax[AA];
    __shared__ float sSum[AA][5][8];
    const float* Kp = g_K[s][l] + i*TT*HDD;
    const float* Vp = g_V[s][l] + i*TT*HDD;
    const float* Qp = g_Q[s]    + i*TT*HDD;
    bool valid = tid < TT;
    int b = valid ? tid : 0;

    if (l == 0) gwait();                 // l=0: K/V/Q all from predecessor

    float kb[HDD], vv[HDD];
    #pragma unroll
    for (int e=0;e<HDD;e++){
        kb[e] = Kp[b*HDD+e];
        vv[e] = valid ? Vp[b*HDD+e] : 0.f;
    }
    {   // vbar partials
        float p[HDD];
        #pragma unroll
        for (int e=0;e<HDD;e++) p[e] = warpsum(vv[e]);
        if (lane==0){
            #pragma unroll
            for (int e=0;e<HDD;e++) sP[w][e] = p[e];
        }
    }
    __syncthreads();
    if (tid < HDD){
        float acc = 0.f;
        #pragma unroll
        for (int ww=0;ww<5;ww++) acc += sP[ww][tid];
        sVbar[tid] = acc * (1.f/TT);
    }
    __syncthreads();
    if (valid){
        #pragma unroll
        for (int e=0;e<HDD;e++)
            sVh[tid][e] = __float2half2_rn(vv[e] + sVbar[e]);
    }

    if (l != 0) gwait();                 // l>0: only Q is from predecessor

    if (tid < AA*HDD) sQa[tid] = Qp[a0*HDD + tid];
    __syncthreads();

    // kq in fp16x2 (a-pairs)
    __half2 kq[5][HDD];
    #pragma unroll
    for (int p=0;p<5;p++)
        #pragma unroll
        for (int e=0;e<HDD;e++)
            kq[p][e] = __floats2half2_rn(sQa[(2*p)*HDD+e]*kb[e],
                                         sQa[(2*p+1)*HDD+e]*kb[e]);
    // prefetch qb for the epilogue (hide the load behind the scan)
    float qb[HDD];
    #pragma unroll
    for (int e=0;e<HDD;e++) qb[e] = Qp[b*HDD+e];

    __half2 mx2[5];
    #pragma unroll
    for (int p=0;p<5;p++) mx2[p] = __floats2half2_rn(-60000.f, -60000.f);

    #pragma unroll 2
    for (int c=0;c<TT;c++){
        uint4 u0 = *reinterpret_cast<const uint4*>(&sVh[c][0]);
        uint2 u1 = *reinterpret_cast<const uint2*>(&sVh[c][4]);
        __half2 v0 = *(__half2*)&u0.x, v1 = *(__half2*)&u0.y;
        __half2 v2 = *(__half2*)&u0.z, v3 = *(__half2*)&u0.w;
        __half2 v4 = *(__half2*)&u1.x, v5 = *(__half2*)&u1.y;
        #pragma unroll
        for (int p=0;p<5;p++){
            __half2 acc = __hmul2(kq[p][0], v0);
            acc = __hfma2(kq[p][1], v1, acc);
            acc = __hfma2(kq[p][2], v2, acc);
            acc = __hfma2(kq[p][3], v3, acc);
            acc = __hfma2(kq[p][4], v4, acc);
            acc = __hfma2(kq[p][5], v5, acc);
            mx2[p] = __hmax2(mx2[p], acc);
        }
    }
    float fx[AA];
    #pragma unroll
    for (int p=0;p<5;p++){
        fx[2*p]   = __low2float(mx2[p]);
        fx[2*p+1] = __high2float(mx2[p]);
    }

    // ---- batched epilogue ----
    #pragma unroll
    for (int a=0;a<AA;a++){
        float mm = valid ? fx[a] : -INFINITY;
        #pragma unroll
        for (int o=16;o>0;o>>=1) mm = fmaxf(mm, __shfl_xor_sync(0xffffffffu, mm, o));
        if (lane==0) sMax[a][w] = mm;
    }
    __syncthreads();
    if (tid < AA){
        float mm = sMax[tid][0];
        #pragma unroll
        for (int ww=1;ww<5;ww++) mm = fmaxf(mm, sMax[tid][ww]);
        sBMax[tid] = mm;
    }
    __syncthreads();
    #pragma unroll
    for (int a=0;a<AA;a++){
        float ex = valid ? __expf(fx[a] - sBMax[a]) : 0.f;
        float v7[7];
        #pragma unroll
        for (int e=0;e<HDD;e++) v7[e] = ex*qb[e];
        v7[6] = ex;
        #pragma unroll
        for (int j=0;j<7;j++){
            float v = v7[j];
            #pragma unroll
            for (int o=16;o>0;o>>=1) v += __shfl_xor_sync(0xffffffffu, v, o);
            if (lane==0) sSum[a][w][j] = v;
        }
    }
    __syncthreads();
    if (tid < AA*HDD){
        int a = tid / HDD, e = tid % HDD;
        float num=0.f, den=0.f;
        #pragma unroll
        for (int ww=0;ww<5;ww++){ num += sSum[a][ww][e]; den += sSum[a][ww][6]; }
        int b_ = i/HH, h_ = i%HH;
        g_attn[s][((a0+a)*BB + b_)*DD + h_*HDD + e] = num/den;
    }
    gtrig();
}

// ---------------- 3. out-proj + residual + LN + FFN + residual + Q(l+1) --
// PDL: weights + g_h are independent of immediate predecessor (k_att) ->
// prefetch to L1 before gwait; g_attn read after gwait.
__global__ void k_ffnq(const float* __restrict__ out_w, const float* __restrict__ out_b,
                       const float* __restrict__ w1, const float* __restrict__ b1,
                       const float* __restrict__ w2, const float* __restrict__ b2,
                       const float* __restrict__ n2g, const float* __restrict__ n2b,
                       const float* __restrict__ in_w, const float* __restrict__ in_b,
                       const float* __restrict__ n1g, const float* __restrict__ n1b, int l){
    int w = threadIdx.x >> 5, lane = threadIdx.x & 31;
    int idx = blockIdx.x*4 + w;           // 2*T*B rows
    int b = idx % BB; idx /= BB;
    int t = idx % TT; int s = idx / TT;
    __shared__ float sA[4][DD], sXn[4][DD], sHid[4][4*DD];
    int ro = (t*BB+b)*DD;
    int pl_ = s*LL+l;
    // ---- pre-wait: independent loads / prefetches ----
    float h0 = (lane<DD) ? g_h[s][ro+lane] : 0.f;
    if (lane<DD){
        pfL1(out_w + pl_*DD*DD + lane*DD);
        pfL1(w2 + pl_*DD*4*DD + lane*4*DD);
        pfL1(w2 + pl_*DD*4*DD + lane*4*DD + 32);
        pfL1(w2 + pl_*DD*4*DD + lane*4*DD + 64);
        pfL1(w2 + pl_*DD*4*DD + lane*4*DD + 96);
    }
    for (int j=lane; j<4*DD; j+=32) pfL1(w1 + pl_*4*DD*DD + j*DD);
    gwait();
    // ---- dependent part ----
    if (lane<DD) sA[w][lane] = g_attn[s][ro+lane];
    __syncwarp();
    float x = 0.f;
    if (lane<DD){
        const float* wr = out_w + pl_*DD*DD + lane*DD;
        float acc = out_b[pl_*DD + lane];
        #pragma unroll
        for (int j=0;j<DD;j++) acc = fmaf(sA[w][j], wr[j], acc);
        x = h0 + acc;                     // residual
    }
    float sum = warpsum(x), sq = warpsum(x*x);
    float m = sum*(1.f/DD), var = sq*(1.f/DD)-m*m, r = rsqrtf(var+1e-5f);
    if (lane<DD) sXn[w][lane] = (x-m)*r*n2g[pl_*DD+lane] + n2b[pl_*DD+lane];
    __syncwarp();
    for (int j=lane; j<4*DD; j+=32){
        const float* wr = w1 + pl_*4*DD*DD + j*DD;
        float acc = b1[pl_*4*DD + j];
        #pragma unroll
        for (int q=0;q<DD;q++) acc = fmaf(sXn[w][q], wr[q], acc);
        sHid[w][j] = fmaxf(acc, 0.f);
    }
    __syncwarp();
    float hnew = 0.f;
    if (lane<DD){
        const float* wr = w2 + pl_*DD*4*DD + lane*4*DD;
        float acc = b2[pl_*DD + lane];
        #pragma unroll 4
        for (int j=0;j<4*DD;j++) acc = fmaf(sHid[w][j], wr[j], acc);
        hnew = x + acc;                   // residual 2
        g_h[s][ro+lane] = hnew;
    }
    if (l+1 < LL){
        // fused Q projection for next layer
        float sum2 = warpsum(hnew), sq2 = warpsum(hnew*hnew);
        float m2 = sum2*(1.f/DD), var2 = sq2*(1.f/DD)-m2*m2, r2 = rsqrtf(var2+1e-5f);
        int pb = (pl_+1)*DD;
        if (lane<DD) sA[w][lane] = (hnew-m2)*r2*n1g[pb+lane] + n1b[pb+lane];
        __syncwarp();
        if (lane<DD){
            const float* iw = in_w + (pl_+1)*3*DD*DD + lane*DD;
            float acc = in_b[(pl_+1)*3*DD + lane];
            #pragma unroll
            for (int j=0;j<DD;j++) acc = fmaf(sA[w][j], iw[j], acc);
            acc *= 0.4082482904638631f;
            int i = b*HH + lane/HDD, e = lane%HDD;
            g_Q[s][(i*TT+t)*HDD+e] = acc;
        }
    }
    gtrig();
}

// ---------------- 4. head: concat last timestep, proj MLP, output --------
__global__ void k_head(const float* __restrict__ p1w, const float* __restrict__ p1b,
                       const float* __restrict__ p2w, const float* __restrict__ p2b,
                       const float* __restrict__ ow, const float* __restrict__ ob,
                       float* __restrict__ out){
    int tid = threadIdx.x;                // 64 threads
    __shared__ float sLast[BB*2*DD], sHid[2*DD], sC[2*DD];
    // pre-wait: prefetch head weights (independent of g_h)
    if (tid < 2*DD){
        for (int j=0;j<2*DD;j+=32){ pfL1(p1w + tid*2*DD + j); pfL1(p2w + tid*2*DD + j); }
    }
    gwait();
    for (int idx=tid; idx<BB*2*DD; idx+=64){
        int b = idx/(2*DD), j = idx%(2*DD);
        float v = (j<DD) ? g_h[0][((TT-1)*BB+b)*DD + j]
                         : g_h[1][((TT-1)*BB+b)*DD + (j-DD)];
        sLast[idx] = v;
        out[BB + idx] = v;                // last_hs after out[0:8]
    }
    __syncthreads();
    for (int b=0;b<BB;b++){
        if (tid < 2*DD){
            float acc = p1b[tid];
            const float* wr = p1w + tid*2*DD;
            for (int j=0;j<2*DD;j++) acc = fmaf(sLast[b*2*DD+j], wr[j], acc);
            sHid[tid] = fmaxf(acc, 0.f);
        }
        __syncthreads();
        if (tid < 2*DD){
            float acc = p2b[tid];
            const float* wr = p2w + tid*2*DD;
            for (int j=0;j<2*DD;j++) acc = fmaf(sHid[j], wr[j], acc);
            acc += sLast[b*2*DD+tid];     // residual
            sC[tid] = acc * ow[tid];
        }
        __syncthreads();
        if (tid==0){
            float acc = ob[0];
            for (int j=0;j<2*DD;j++) acc += sC[j];
            out[b] = acc;
        }
        __syncthreads();
    }
}

// -------------------------------------------------------------------------
static inline void launch_pdl(void* fn, dim3 gd, dim3 bd, void** args){
    cudaLaunchConfig_t cfg = {};
    cfg.gridDim = gd; cfg.blockDim = bd;
    cfg.dynamicSmemBytes = 0; cfg.stream = 0;
    cudaLaunchAttribute attr[1];
    attr[0].id = cudaLaunchAttributeProgrammaticStreamSerialization;
    attr[0].val.programmaticStreamSerializationAllowed = 1;
    cfg.attrs = attr; cfg.numAttrs = 1;
    cudaLaunchKernelExC(&cfg, fn, args);
}

extern "C" void kernel_launch(void* const* d_in, const int* in_sizes, int n_in,
                              void* d_out, int out_size){
    const float* xl   = (const float*)d_in[0];
    const float* xa   = (const float*)d_in[1];
    const float* xv   = (const float*)d_in[2];
    const float* Wl   = (const float*)d_in[3];
    const float* Wa   = (const float*)d_in[4];
    const float* Wv   = (const float*)d_in[5];
    const float* in_w = (const float*)d_in[6];
    const float* in_b = (const float*)d_in[7];
    const float* outw = (const float*)d_in[8];
    const float* outb = (const float*)d_in[9];
    const float* l1w  = (const float*)d_in[10];
    const float* l1b  = (const float*)d_in[11];
    const float* l2w  = (const float*)d_in[12];
    const float* l2b  = (const float*)d_in[13];
    const float* n1g  = (const float*)d_in[14];
    const float* n1b  = (const float*)d_in[15];
    const float* n2g  = (const float*)d_in[16];
    const float* n2b  = (const float*)d_in[17];
    const float* p1w  = (const float*)d_in[18];
    const float* p1b  = (const float*)d_in[19];
    const float* p2w  = (const float*)d_in[20];
    const float* p2b  = (const float*)d_in[21];
    const float* ow   = (const float*)d_in[22];
    const float* ob   = (const float*)d_in[23];
    float* out = (float*)d_out;

    k_pre<<<TT*BB, 96>>>(xl, xa, xv, Wl, Wa, Wv, in_w, in_b, n1g, n1b);
    for (int l=0; l<LL; l++){
        {
            void* args[] = { &l };
            launch_pdl((void*)k_att, dim3(TT/AA, NI, 2), dim3(160,1,1), args);
        }
        {
            void* args[] = { (void*)&outw, (void*)&outb, (void*)&l1w, (void*)&l1b,
                             (void*)&l2w, (void*)&l2b, (void*)&n2g, (void*)&n2b,
                             (void*)&in_w, (void*)&in_b, (void*)&n1g, (void*)&n1b, &l };
            launch_pdl((void*)k_ffnq, dim3(2*TT*BB/4,1,1), dim3(128,1,1), args);
        }
    }
    {
        void* args[] = { (void*)&p1w, (void*)&p1b, (void*)&p2w, (void*)&p2b,
                         (void*)&ow, (void*)&ob, (void*)&out };
        launch_pdl((void*)k_head, dim3(1,1,1), dim3(64,1,1), args);
    }
}